// round 1
// baseline (speedup 1.0000x reference)
#include <cuda_runtime.h>

// Grouped mean over skeleton nodes:
//   in  : [32, 512, 21, 256] f32   (bt = 16384 rows of 21*256)
//   out : [32, 512, 10, 256] f32
// NODE_MAP = [[1,2],[3,4],[5,6],[7,8],[0,9],[10,11,12],[13,14],[15,16],[17,18],[19,20]]

__constant__ int   c_n0[10]    = {1, 3, 5, 7, 0, 10, 13, 15, 17, 19};
__constant__ int   c_n1[10]    = {2, 4, 6, 8, 9, 11, 14, 16, 18, 20};
__constant__ int   c_n2[10]    = {-1, -1, -1, -1, -1, 12, -1, -1, -1, -1};
__constant__ float c_scale[10] = {0.5f, 0.5f, 0.5f, 0.5f, 0.5f,
                                  1.0f / 3.0f, 0.5f, 0.5f, 0.5f, 0.5f};

// Per bt-row: input is 21 nodes * 64 float4; output is 10 nodes * 64 float4.
static constexpr int C4       = 64;          // 256 f32 / 4
static constexpr int IN_ROW4  = 21 * C4;     // 1344 float4 per bt row (input)
static constexpr int OUT_ROW4 = 10 * C4;     // 640 float4 per bt row (output)

__global__ __launch_bounds__(256)
void s_down_sampling_kernel(const float4* __restrict__ in,
                            float4* __restrict__ out,
                            int total4)
{
    int idx = blockIdx.x * blockDim.x + threadIdx.x;
    if (idx >= total4) return;

    int c4 = idx & (C4 - 1);           // channel float4 index 0..63
    int tmp = idx >> 6;                // bt*10 + m
    int m  = tmp % 10;
    int bt = tmp / 10;

    const float4* row = in + (long long)bt * IN_ROW4;

    float4 a = row[c_n0[m] * C4 + c4];
    float4 b = row[c_n1[m] * C4 + c4];

    float sx = a.x + b.x;
    float sy = a.y + b.y;
    float sz = a.z + b.z;
    float sw = a.w + b.w;

    int n2 = c_n2[m];
    if (n2 >= 0) {
        float4 c = row[n2 * C4 + c4];
        sx += c.x; sy += c.y; sz += c.z; sw += c.w;
    }

    float s = c_scale[m];
    float4 r;
    r.x = sx * s;
    r.y = sy * s;
    r.z = sz * s;
    r.w = sw * s;

    out[idx] = r;
}

extern "C" void kernel_launch(void* const* d_in, const int* in_sizes, int n_in,
                              void* d_out, int out_size)
{
    const float4* in  = (const float4*)d_in[0];
    float4*       out = (float4*)d_out;

    // out_size = 32*512*10*256 f32 elements -> /4 float4
    int total4 = out_size / 4;
    int threads = 256;
    int blocks = (total4 + threads - 1) / threads;
    s_down_sampling_kernel<<<blocks, threads>>>(in, out, total4);
}